// round 3
// baseline (speedup 1.0000x reference)
#include <cuda_runtime.h>
#include <math.h>

#define Nn 4096
#define Ff 256
#define Dd 64
#define Hh 4
#define HD 256
#define LALPHA 0.2f

// ---------------- scratch (device globals; no allocation) ----------------
__device__ __align__(16) float g_h[Hh * Nn * Dd];     // per-head features [H][N][D]
__device__ __align__(16) float g_h1[Nn * HD];         // layer-1 output [N][H*D]
__device__ __align__(16) float g_f1[Hh * Nn];
__device__ __align__(16) float g_f2[Hh * Nn];
__device__ __align__(16) float g_G1[Hh * Nn];
__device__ __align__(16) float g_G1p[Hh * Nn];
__device__ __align__(16) float g_E2[Hh * Nn];
__device__ __align__(16) float g_E2p[Hh * Nn];
__device__ float g_f2max[Hh];

// ---------------- packed f32x2 helpers ----------------
#define FMA2(d, a, b) asm("fma.rn.f32x2 %0, %1, %2, %3;" : "=l"(d) : "l"(a), "l"(b), "l"(d))

static __device__ __forceinline__ unsigned long long packdup(float v) {
    unsigned long long r;
    unsigned u = __float_as_uint(v);
    asm("mov.b64 %0, {%1, %1};" : "=l"(r) : "r"(u));
    return r;
}

// =====================================================================
// K1: feature GEMM   Hout[h][n][d] = sum_f X[n][f] * W[h][f][d]
//     X is [N, 256] (x or g_h1), W is [H, 256, 64]
// grid (N/64, H), block 256
// =====================================================================
__global__ __launch_bounds__(256) void feat_gemm_kernel(
    const float* __restrict__ X, const float* __restrict__ W, int use_h1)
{
    const float* Xp = use_h1 ? g_h1 : X;
    const int head = blockIdx.y;
    const int i0 = blockIdx.x * 64;

    __shared__ __align__(16) float sXT[32][68];
    __shared__ __align__(16) float sWs[32][64];

    const int t = threadIdx.x;
    const int tx = t & 15, ty = t >> 4;
    const int c0 = tx * 4, r0 = ty * 4;

    float acc[4][4] = {};

    for (int kt = 0; kt < Ff; kt += 32) {
#pragma unroll
        for (int q = 0; q < 2; q++) {
            int idx = t + 256 * q;
            int row = idx >> 3;
            int k0 = (idx & 7) * 4;
            float4 v = *reinterpret_cast<const float4*>(Xp + (size_t)(i0 + row) * Ff + kt + k0);
            sXT[k0 + 0][row] = v.x;
            sXT[k0 + 1][row] = v.y;
            sXT[k0 + 2][row] = v.z;
            sXT[k0 + 3][row] = v.w;
        }
#pragma unroll
        for (int q = 0; q < 2; q++) {
            int idx = t + 256 * q;
            int kk = idx >> 4;
            int cc = (idx & 15) * 4;
            *reinterpret_cast<float4*>(&sWs[kk][cc]) =
                *reinterpret_cast<const float4*>(W + (size_t)(head * Ff + kt + kk) * Dd + cc);
        }
        __syncthreads();
#pragma unroll
        for (int k = 0; k < 32; k++) {
            float4 xv = *reinterpret_cast<const float4*>(&sXT[k][r0]);
            float4 wv = *reinterpret_cast<const float4*>(&sWs[k][c0]);
            acc[0][0] += xv.x * wv.x; acc[0][1] += xv.x * wv.y; acc[0][2] += xv.x * wv.z; acc[0][3] += xv.x * wv.w;
            acc[1][0] += xv.y * wv.x; acc[1][1] += xv.y * wv.y; acc[1][2] += xv.y * wv.z; acc[1][3] += xv.y * wv.w;
            acc[2][0] += xv.z * wv.x; acc[2][1] += xv.z * wv.y; acc[2][2] += xv.z * wv.z; acc[2][3] += xv.z * wv.w;
            acc[3][0] += xv.w * wv.x; acc[3][1] += xv.w * wv.y; acc[3][2] += xv.w * wv.z; acc[3][3] += xv.w * wv.w;
        }
        __syncthreads();
    }
#pragma unroll
    for (int r = 0; r < 4; r++) {
        float4 o = make_float4(acc[r][0], acc[r][1], acc[r][2], acc[r][3]);
        *reinterpret_cast<float4*>(g_h + (size_t)(head * Nn + i0 + r0 + r) * Dd + c0) = o;
    }
}

// =====================================================================
// K2: f1/f2 dots.  One warp per (head, node).
// f1[h][n] = h[h][n][:] . a[h][0:64];  f2 with a[h][64:128]
// =====================================================================
__global__ __launch_bounds__(128) void f12_kernel(const float* __restrict__ a)
{
    int warp = (blockIdx.x * blockDim.x + threadIdx.x) >> 5;
    int lane = threadIdx.x & 31;
    if (warp >= Hh * Nn) return;
    int head = warp >> 12;  // / Nn
    const float* hr = g_h + (size_t)warp * Dd;
    float v0 = hr[lane], v1 = hr[lane + 32];
    const float* ah = a + head * 2 * Dd;
    float s1 = v0 * ah[lane] + v1 * ah[lane + 32];
    float s2 = v0 * ah[64 + lane] + v1 * ah[64 + lane + 32];
#pragma unroll
    for (int o = 16; o; o >>= 1) {
        s1 += __shfl_xor_sync(0xffffffffu, s1, o);
        s2 += __shfl_xor_sync(0xffffffffu, s2, o);
    }
    if (lane == 0) { g_f1[warp] = s1; g_f2[warp] = s2; }
}

// =====================================================================
// K3: per-head max of f2
// =====================================================================
__global__ void f2max_kernel()
{
    int head = blockIdx.x;
    __shared__ float sm[256];
    float m = -1e30f;
    for (int n = threadIdx.x; n < Nn; n += 256) m = fmaxf(m, g_f2[head * Nn + n]);
    sm[threadIdx.x] = m;
    __syncthreads();
    for (int o = 128; o; o >>= 1) {
        if (threadIdx.x < o) sm[threadIdx.x] = fmaxf(sm[threadIdx.x], sm[threadIdx.x + o]);
        __syncthreads();
    }
    if (threadIdx.x == 0) g_f2max[head] = sm[0];
}

// =====================================================================
// K4: per-node weight prep (separable softmax factors)
// =====================================================================
__global__ void wprep_kernel()
{
    int idx = blockIdx.x * 256 + threadIdx.x;   // Hh*Nn total
    int head = idx >> 12;
    float f1 = g_f1[idx], f2 = g_f2[idx];
    float m = f1 + g_f2max[head];
    m = (m >= 0.f) ? m : LALPHA * m;            // m_i = LR(f1_i + max f2) >= true row max
    g_G1[idx]  = expf(f1 - m);
    g_G1p[idx] = expf(LALPHA * f1 - m);
    g_E2[idx]  = expf(f2);
    g_E2p[idx] = expf(LALPHA * f2);
}

// =====================================================================
// K5: attention aggregation  out[i][head*64+d] = elu( (sum_j w_ij h_j) / sum_j w_ij )
//     w_ij generated on the fly from adj + per-node factors.
// Block tile: 64 rows x 64 cols (one head), K tiles of 32.  grid (N/64, H), 256 threads.
// =====================================================================
__global__ __launch_bounds__(256) void attn_kernel(
    const int* __restrict__ adj, float* __restrict__ outp, int to_h1)
{
    float* op = to_h1 ? g_h1 : outp;
    const int head = blockIdx.y;
    const int i0 = blockIdx.x * 64;

    __shared__ __align__(16) float sW[32][68];   // w transposed: [k][row]
    __shared__ __align__(16) float sH[32][64];   // h tile: [k][d]
    __shared__ float sRow[64];
    __shared__ float sF1[64], sG1[64], sG1p[64];

    const int t = threadIdx.x;
    if (t < 64) {
        int gi = head * Nn + i0 + t;
        sF1[t] = g_f1[gi];
        sG1[t] = g_G1[gi];
        sG1p[t] = g_G1p[gi];
        sRow[t] = 0.f;
    }

    // generation mapping: thread handles 2 (row, k-quad) slots
    const int grow0 = t >> 3;        // 0..31 (p=0), +32 (p=1)
    const int gk0 = (t & 7) * 4;
    // compute mapping: 4 rows x 4 cols micro-tile
    const int tx = t & 15, ty = t >> 4;
    const int c0 = tx * 4, r0 = ty * 4;

    unsigned long long acc[4][2] = {};   // 4 rows x 2 f32x2 pairs

    // prefetch tile 0
    int4 aReg0, aReg1;
    float4 pf2, pe2, pe2p;
    {
        const int base = head * Nn + gk0;
        pf2  = *reinterpret_cast<const float4*>(g_f2 + base);
        pe2  = *reinterpret_cast<const float4*>(g_E2 + base);
        pe2p = *reinterpret_cast<const float4*>(g_E2p + base);
        aReg0 = *reinterpret_cast<const int4*>(adj + (size_t)(i0 + grow0) * Nn + gk0);
        aReg1 = *reinterpret_cast<const int4*>(adj + (size_t)(i0 + grow0 + 32) * Nn + gk0);
    }
    __syncthreads();

    for (int kt = 0; kt < Nn / 32; kt++) {
        // ---- generate w tile + rowsum partials ----
#pragma unroll
        for (int p = 0; p < 2; p++) {
            const int row = grow0 + 32 * p;
            const float f1r = sF1[row], g1 = sG1[row], g1p = sG1p[row];
            const int4 a4 = (p == 0) ? aReg0 : aReg1;

            float s0 = f1r + pf2.x, s1 = f1r + pf2.y, s2 = f1r + pf2.z, s3 = f1r + pf2.w;
            float w0 = (s0 >= 0.f) ? g1 * pe2.x : g1p * pe2p.x;
            float w1 = (s1 >= 0.f) ? g1 * pe2.y : g1p * pe2p.y;
            float w2 = (s2 >= 0.f) ? g1 * pe2.z : g1p * pe2p.z;
            float w3 = (s3 >= 0.f) ? g1 * pe2.w : g1p * pe2p.w;
            w0 = (a4.x != 0) ? w0 : 0.f;
            w1 = (a4.y != 0) ? w1 : 0.f;
            w2 = (a4.z != 0) ? w2 : 0.f;
            w3 = (a4.w != 0) ? w3 : 0.f;
            sW[gk0 + 0][row] = w0;
            sW[gk0 + 1][row] = w1;
            sW[gk0 + 2][row] = w2;
            sW[gk0 + 3][row] = w3;
            float partial = (w0 + w1) + (w2 + w3);
            partial += __shfl_xor_sync(0xffffffffu, partial, 1);
            partial += __shfl_xor_sync(0xffffffffu, partial, 2);
            partial += __shfl_xor_sync(0xffffffffu, partial, 4);
            if ((t & 7) == 0) sRow[row] += partial;   // rows unique per (warp, p)
        }
        // ---- load h tile ----
        {
            const float* hb = g_h + (size_t)(head * Nn + kt * 32) * Dd;
#pragma unroll
            for (int q = 0; q < 2; q++) {
                int idx = t + 256 * q;
                int kk = idx >> 4, cc = (idx & 15) * 4;
                *reinterpret_cast<float4*>(&sH[kk][cc]) =
                    *reinterpret_cast<const float4*>(hb + kk * Dd + cc);
            }
        }
        __syncthreads();

        // ---- prefetch next tile (consumed next iteration) ----
        if (kt + 1 < Nn / 32) {
            const int kb = (kt + 1) * 32 + gk0;
            const int base = head * Nn + kb;
            pf2  = *reinterpret_cast<const float4*>(g_f2 + base);
            pe2  = *reinterpret_cast<const float4*>(g_E2 + base);
            pe2p = *reinterpret_cast<const float4*>(g_E2p + base);
            aReg0 = *reinterpret_cast<const int4*>(adj + (size_t)(i0 + grow0) * Nn + kb);
            aReg1 = *reinterpret_cast<const int4*>(adj + (size_t)(i0 + grow0 + 32) * Nn + kb);
        }

        // ---- GEMM fragment: packed f32x2 FFMA ----
#pragma unroll
        for (int k = 0; k < 32; k++) {
            float4 wq = *reinterpret_cast<const float4*>(&sW[k][r0]);
            ulonglong2 hp = *reinterpret_cast<const ulonglong2*>(&sH[k][c0]);
            unsigned long long wp;
            wp = packdup(wq.x); FMA2(acc[0][0], wp, hp.x); FMA2(acc[0][1], wp, hp.y);
            wp = packdup(wq.y); FMA2(acc[1][0], wp, hp.x); FMA2(acc[1][1], wp, hp.y);
            wp = packdup(wq.z); FMA2(acc[2][0], wp, hp.x); FMA2(acc[2][1], wp, hp.y);
            wp = packdup(wq.w); FMA2(acc[3][0], wp, hp.x); FMA2(acc[3][1], wp, hp.y);
        }
        __syncthreads();
    }

    // ---- epilogue: normalize, ELU, store ----
#pragma unroll
    for (int r = 0; r < 4; r++) {
        float inv = 1.0f / sRow[r0 + r];
        unsigned u0, u1, u2, u3;
        asm("mov.b64 {%0, %1}, %2;" : "=r"(u0), "=r"(u1) : "l"(acc[r][0]));
        asm("mov.b64 {%0, %1}, %2;" : "=r"(u2), "=r"(u3) : "l"(acc[r][1]));
        float v0 = __uint_as_float(u0) * inv;
        float v1 = __uint_as_float(u1) * inv;
        float v2 = __uint_as_float(u2) * inv;
        float v3 = __uint_as_float(u3) * inv;
        float4 o;
        o.x = (v0 > 0.f) ? v0 : expm1f(v0);
        o.y = (v1 > 0.f) ? v1 : expm1f(v1);
        o.z = (v2 > 0.f) ? v2 : expm1f(v2);
        o.w = (v3 > 0.f) ? v3 : expm1f(v3);
        *reinterpret_cast<float4*>(op + (size_t)(i0 + r0 + r) * HD + head * Dd + c0) = o;
    }
}

// =====================================================================
// launch
// =====================================================================
extern "C" void kernel_launch(void* const* d_in, const int* in_sizes, int n_in,
                              void* d_out, int out_size)
{
    (void)in_sizes; (void)n_in; (void)out_size;
    const float* x  = (const float*)d_in[1];
    const int*   adj = (const int*)d_in[2];
    const float* W1 = (const float*)d_in[3];
    const float* a1 = (const float*)d_in[4];
    const float* W2 = (const float*)d_in[5];
    const float* a2 = (const float*)d_in[6];
    float* out = (float*)d_out;

    dim3 gGemm(Nn / 64, Hh);
    int f12Blocks = (Hh * Nn) / 4;           // 4 warps (128 threads) per block

    // ---- layer 1 ----
    feat_gemm_kernel<<<gGemm, 256>>>(x, W1, 0);
    f12_kernel<<<f12Blocks, 128>>>(a1);
    f2max_kernel<<<Hh, 256>>>();
    wprep_kernel<<<(Hh * Nn) / 256, 256>>>();
    attn_kernel<<<gGemm, 256>>>(adj, nullptr, 1);   // -> g_h1

    // ---- layer 2 ----
    feat_gemm_kernel<<<gGemm, 256>>>(nullptr, W2, 1);
    f12_kernel<<<f12Blocks, 128>>>(a2);
    f2max_kernel<<<Hh, 256>>>();
    wprep_kernel<<<(Hh * Nn) / 256, 256>>>();
    attn_kernel<<<gGemm, 256>>>(adj, out, 0);       // -> d_out
}

// round 6
// speedup vs baseline: 1.6446x; 1.6446x over previous
#include <cuda_runtime.h>
#include <cuda_fp16.h>
#include <cstdint>
#include <math.h>

#define Nn 4096
#define Ff 256
#define Dd 64
#define Hh 4
#define HD 256
#define NW 128            // adj bitmask words per row (4096/32)
#define LALPHA 0.2f

// ---------------- scratch (device globals; no allocation) ----------------
__device__ __align__(16) float g_h[Hh * Nn * Dd];     // [H][N][D] for f1/f2 dots
__device__ __align__(16) float g_h1[Nn * HD];         // layer-1 output [N][H*D]
__device__ __align__(16) __half g_hTh[Hh * Dd * Nn];  // fp16 hi of h, transposed [H][D][N]
__device__ __align__(16) __half g_hTl[Hh * Dd * Nn];  // fp16 residual lo [H][D][N]
__device__ __align__(16) float g_f1[Hh * Nn];
__device__ __align__(16) float g_f2[Hh * Nn];
__device__ __align__(16) float g_G1[Hh * Nn];
__device__ __align__(16) float g_G1p[Hh * Nn];
__device__ __align__(16) float g_E2[Hh * Nn];
__device__ __align__(16) float g_E2p[Hh * Nn];
__device__ float g_f2max[Hh];
__device__ unsigned g_adjp[Nn * NW];                  // packed adjacency bits

// ---------------- helpers ----------------
static __device__ __forceinline__ uint32_t smem_u32(const void* p) {
    uint32_t a;
    asm("{ .reg .u64 t; cvta.to.shared.u64 t, %1; cvt.u32.u64 %0, t; }" : "=r"(a) : "l"(p));
    return a;
}

#define LDSM4(R, addr) \
    asm volatile("ldmatrix.sync.aligned.m8n8.x4.shared.b16 {%0,%1,%2,%3}, [%4];" \
                 : "=r"((R)[0]), "=r"((R)[1]), "=r"((R)[2]), "=r"((R)[3]) : "r"(addr))

#define MMA16816(C, A, B0, B1) \
    asm volatile("mma.sync.aligned.m16n8k16.row.col.f32.f16.f16.f32 " \
                 "{%0,%1,%2,%3}, {%4,%5,%6,%7}, {%8,%9}, {%0,%1,%2,%3};" \
                 : "+f"((C)[0]), "+f"((C)[1]), "+f"((C)[2]), "+f"((C)[3]) \
                 : "r"((A)[0]), "r"((A)[1]), "r"((A)[2]), "r"((A)[3]), "r"(B0), "r"(B1))

// =====================================================================
// K0: pack adjacency into bitmask
// =====================================================================
__global__ void pack_adj_kernel(const int* __restrict__ adj)
{
    int w = blockIdx.x * 8 + (threadIdx.x >> 5);
    int lane = threadIdx.x & 31;
    int v = adj[(size_t)w * 32 + lane];
    unsigned m = __ballot_sync(0xffffffffu, v != 0);
    if (lane == 0) g_adjp[w] = m;
}

// =====================================================================
// K1: feature GEMM  h[h][n][d] = sum_f X[n][f] W[h][f][d]
//     also emits fp16 hi/lo transposed copies for the MMA B operand.
// =====================================================================
__global__ __launch_bounds__(256) void feat_gemm_kernel(
    const float* __restrict__ X, const float* __restrict__ W, int use_h1)
{
    const float* Xp = use_h1 ? g_h1 : X;
    const int head = blockIdx.y;
    const int i0 = blockIdx.x * 64;

    __shared__ __align__(16) float sXT[32][68];
    __shared__ __align__(16) float sWs[32][64];

    const int t = threadIdx.x;
    const int tx = t & 15, ty = t >> 4;
    const int c0 = tx * 4, r0 = ty * 4;

    float acc[4][4] = {};

    for (int kt = 0; kt < Ff; kt += 32) {
#pragma unroll
        for (int q = 0; q < 2; q++) {
            int idx = t + 256 * q;
            int row = idx >> 3;
            int k0 = (idx & 7) * 4;
            float4 v = *reinterpret_cast<const float4*>(Xp + (size_t)(i0 + row) * Ff + kt + k0);
            sXT[k0 + 0][row] = v.x;
            sXT[k0 + 1][row] = v.y;
            sXT[k0 + 2][row] = v.z;
            sXT[k0 + 3][row] = v.w;
        }
#pragma unroll
        for (int q = 0; q < 2; q++) {
            int idx = t + 256 * q;
            int kk = idx >> 4;
            int cc = (idx & 15) * 4;
            *reinterpret_cast<float4*>(&sWs[kk][cc]) =
                *reinterpret_cast<const float4*>(W + (size_t)(head * Ff + kt + kk) * Dd + cc);
        }
        __syncthreads();
#pragma unroll
        for (int k = 0; k < 32; k++) {
            float4 xv = *reinterpret_cast<const float4*>(&sXT[k][r0]);
            float4 wv = *reinterpret_cast<const float4*>(&sWs[k][c0]);
            acc[0][0] += xv.x * wv.x; acc[0][1] += xv.x * wv.y; acc[0][2] += xv.x * wv.z; acc[0][3] += xv.x * wv.w;
            acc[1][0] += xv.y * wv.x; acc[1][1] += xv.y * wv.y; acc[1][2] += xv.y * wv.z; acc[1][3] += xv.y * wv.w;
            acc[2][0] += xv.z * wv.x; acc[2][1] += xv.z * wv.y; acc[2][2] += xv.z * wv.z; acc[2][3] += xv.z * wv.w;
            acc[3][0] += xv.w * wv.x; acc[3][1] += xv.w * wv.y; acc[3][2] += xv.w * wv.z; acc[3][3] += xv.w * wv.w;
        }
        __syncthreads();
    }
#pragma unroll
    for (int r = 0; r < 4; r++) {
        float4 o = make_float4(acc[r][0], acc[r][1], acc[r][2], acc[r][3]);
        *reinterpret_cast<float4*>(g_h + (size_t)(head * Nn + i0 + r0 + r) * Dd + c0) = o;
#pragma unroll
        for (int c = 0; c < 4; c++) {
            float v = acc[r][c];
            __half hhi = __float2half_rn(v);
            size_t tix = (size_t)(head * Dd + c0 + c) * Nn + i0 + r0 + r;
            g_hTh[tix] = hhi;
            g_hTl[tix] = __float2half_rn(v - __half2float(hhi));
        }
    }
}

// =====================================================================
// K2: f1/f2 dots (one warp per head,node)
// =====================================================================
__global__ __launch_bounds__(128) void f12_kernel(const float* __restrict__ a)
{
    int warp = (blockIdx.x * blockDim.x + threadIdx.x) >> 5;
    int lane = threadIdx.x & 31;
    if (warp >= Hh * Nn) return;
    int head = warp >> 12;
    const float* hr = g_h + (size_t)warp * Dd;
    float v0 = hr[lane], v1 = hr[lane + 32];
    const float* ah = a + head * 2 * Dd;
    float s1 = v0 * ah[lane] + v1 * ah[lane + 32];
    float s2 = v0 * ah[64 + lane] + v1 * ah[64 + lane + 32];
#pragma unroll
    for (int o = 16; o; o >>= 1) {
        s1 += __shfl_xor_sync(0xffffffffu, s1, o);
        s2 += __shfl_xor_sync(0xffffffffu, s2, o);
    }
    if (lane == 0) { g_f1[warp] = s1; g_f2[warp] = s2; }
}

// =====================================================================
// K3: per-head max of f2
// =====================================================================
__global__ void f2max_kernel()
{
    int head = blockIdx.x;
    __shared__ float sm[256];
    float m = -1e30f;
    for (int n = threadIdx.x; n < Nn; n += 256) m = fmaxf(m, g_f2[head * Nn + n]);
    sm[threadIdx.x] = m;
    __syncthreads();
    for (int o = 128; o; o >>= 1) {
        if (threadIdx.x < o) sm[threadIdx.x] = fmaxf(sm[threadIdx.x], sm[threadIdx.x + o]);
        __syncthreads();
    }
    if (threadIdx.x == 0) g_f2max[head] = sm[0];
}

// =====================================================================
// K4: per-node separable softmax factors
// =====================================================================
__global__ void wprep_kernel()
{
    int idx = blockIdx.x * 256 + threadIdx.x;
    int head = idx >> 12;
    float f1 = g_f1[idx], f2 = g_f2[idx];
    float m = f1 + g_f2max[head];
    m = (m >= 0.f) ? m : LALPHA * m;
    g_G1[idx]  = expf(f1 - m);
    g_G1p[idx] = expf(LALPHA * f1 - m);
    g_E2[idx]  = expf(f2);
    g_E2p[idx] = expf(LALPHA * f2);
}

// =====================================================================
// K5: attention aggregation via warp-level mma.sync (fp16 split, 3 products)
//   Tile: M=64 rows x N=64 cols per block, K-tiles of 32.
//   grid (Nn/64, Hh) = (64, 4), 256 threads, 2 CTAs/SM.
//   Warp (wm = wid&3, wn = wid>>2): rows [wm*16, +16), cols [wn*32, +32).
// =====================================================================
__global__ __launch_bounds__(256, 2) void attn_mma_kernel(float* __restrict__ outp, int to_h1)
{
    // A: [hi/lo][64 rows][40 halfs] (32 k used, pad 8); B: [hi/lo][64 n][40 halfs]
    __shared__ __align__(16) __half sA[2][64 * 40];
    __shared__ __align__(16) __half sB[2][64 * 40];
    __shared__ float sRow[64], sF1[64], sG1[64], sG1p[64];

    const int head = blockIdx.y;
    const int i0 = blockIdx.x * 64;
    const int t = threadIdx.x;
    const int lane = t & 31;
    const int wid = t >> 5;

    if (t < 64) {
        int gi = head * Nn + i0 + t;
        sF1[t] = g_f1[gi];
        sG1[t] = g_G1[gi];
        sG1p[t] = g_G1p[gi];
    }
    __syncthreads();

    // ---- generation mapping: r = row (0..63), q = k-quarter (8 k each) ----
    const int r = t >> 2, q = t & 3;
    const float f1r = sF1[r], g1 = sG1[r], g1p = sG1p[r];
    const float* f2b  = g_f2  + head * Nn;
    const float* e2b  = g_E2  + head * Nn;
    const float* e2pb = g_E2p + head * Nn;
    const unsigned* adjrow = g_adjp + (size_t)(i0 + r) * NW;

    // ---- B copy mapping: each thread copies 16 halfs of one (arr, d, k-half) ----
    const int barr = t >> 7;           // 0 = hi, 1 = lo
    const int bs2 = t & 127;
    const int bd = bs2 >> 1;
    const int bkh = (bs2 & 1) * 16;
    const __half* bsrc = (barr ? g_hTl : g_hTh) + (size_t)(head * Dd + bd) * Nn + bkh;
    __half* bdst = &sB[barr][bd * 40 + bkh];

    // ---- mma mapping ----
    const int wm = wid & 3, wn = wid >> 2;
    const uint32_t aA  = smem_u32(&sA[0][(wm * 16 + (lane & 15)) * 40 + (lane >> 4) * 8]);
    const uint32_t aAl = aA + 64 * 40 * 2;
    const uint32_t aB0 = smem_u32(&sB[0][(wn * 32 + (lane & 15)) * 40 + (lane >> 4) * 8]);
    const uint32_t aB1 = aB0 + 16 * 40 * 2;
    const uint32_t aB0l = aB0 + 64 * 40 * 2;
    const uint32_t aB1l = aB1 + 64 * 40 * 2;

    float acc[4][4] = {};
    float rsum = 0.f;

    // prefetch kt = 0
    int4 pb0 = *reinterpret_cast<const int4*>(bsrc);
    int4 pb1 = *reinterpret_cast<const int4*>(bsrc + 8);
    unsigned aw = adjrow[0];

    for (int kt = 0; kt < NW; kt++) {
        const int kb = kt * 32;

        // ---- generate A tile (fp32 w -> fp16 hi/lo) + rowsum ----
#pragma unroll
        for (int i = 0; i < 2; i++) {
            const int kq = q * 8 + i * 4;
            const int gk = kb + kq;
            float4 f2v = *reinterpret_cast<const float4*>(f2b + gk);
            float4 e2v = *reinterpret_cast<const float4*>(e2b + gk);
            float4 e2p = *reinterpret_cast<const float4*>(e2pb + gk);
            float w0 = ((aw >> (kq + 0)) & 1) ? ((f1r + f2v.x >= 0.f) ? g1 * e2v.x : g1p * e2p.x) : 0.f;
            float w1 = ((aw >> (kq + 1)) & 1) ? ((f1r + f2v.y >= 0.f) ? g1 * e2v.y : g1p * e2p.y) : 0.f;
            float w2 = ((aw >> (kq + 2)) & 1) ? ((f1r + f2v.z >= 0.f) ? g1 * e2v.z : g1p * e2p.z) : 0.f;
            float w3 = ((aw >> (kq + 3)) & 1) ? ((f1r + f2v.w >= 0.f) ? g1 * e2v.w : g1p * e2p.w) : 0.f;
            rsum += (w0 + w1) + (w2 + w3);
            __half h0 = __float2half_rn(w0), h1 = __float2half_rn(w1);
            __half h2 = __float2half_rn(w2), h3 = __float2half_rn(w3);
            __half2* dh = reinterpret_cast<__half2*>(&sA[0][r * 40 + kq]);
            dh[0] = __halves2half2(h0, h1);
            dh[1] = __halves2half2(h2, h3);
            __half l0 = __float2half_rn(w0 - __half2float(h0));
            __half l1 = __float2half_rn(w1 - __half2float(h1));
            __half l2 = __float2half_rn(w2 - __half2float(h2));
            __half l3 = __float2half_rn(w3 - __half2float(h3));
            __half2* dl = reinterpret_cast<__half2*>(&sA[1][r * 40 + kq]);
            dl[0] = __halves2half2(l0, l1);
            dl[1] = __halves2half2(l2, l3);
        }

        // ---- store prefetched B tile ----
        *reinterpret_cast<int4*>(bdst) = pb0;
        *reinterpret_cast<int4*>(bdst + 8) = pb1;

        // ---- prefetch next tile ----
        if (kt + 1 < NW) {
            pb0 = *reinterpret_cast<const int4*>(bsrc + (kt + 1) * 32);
            pb1 = *reinterpret_cast<const int4*>(bsrc + (kt + 1) * 32 + 8);
            aw = adjrow[kt + 1];
        }
        __syncthreads();

        // ---- mma: 2 k-steps x (2 n-pairs) x 3 products ----
        uint32_t ah[4], al[4], bh[4], bl[4];
#pragma unroll
        for (int kk = 0; kk < 2; kk++) {
            const uint32_t ko = kk * 32;   // +16 halfs
            LDSM4(ah, aA + ko);
            LDSM4(al, aAl + ko);
            LDSM4(bh, aB0 + ko);
            LDSM4(bl, aB0l + ko);
            MMA16816(acc[0], ah, bh[0], bh[2]);
            MMA16816(acc[1], ah, bh[1], bh[3]);
            MMA16816(acc[0], al, bh[0], bh[2]);
            MMA16816(acc[1], al, bh[1], bh[3]);
            MMA16816(acc[0], ah, bl[0], bl[2]);
            MMA16816(acc[1], ah, bl[1], bl[3]);
            LDSM4(bh, aB1 + ko);
            LDSM4(bl, aB1l + ko);
            MMA16816(acc[2], ah, bh[0], bh[2]);
            MMA16816(acc[3], ah, bh[1], bh[3]);
            MMA16816(acc[2], al, bh[0], bh[2]);
            MMA16816(acc[3], al, bh[1], bh[3]);
            MMA16816(acc[2], ah, bl[0], bl[2]);
            MMA16816(acc[3], ah, bl[1], bl[3]);
        }
        __syncthreads();
    }

    // ---- rowsum finalize (exact fp32) ----
    rsum += __shfl_xor_sync(0xffffffffu, rsum, 1);
    rsum += __shfl_xor_sync(0xffffffffu, rsum, 2);
    if (q == 0) sRow[r] = rsum;
    __syncthreads();

    // ---- epilogue: normalize + ELU + store ----
    const int g = lane >> 2;
    const int row0 = wm * 16 + g;
    const float inv0 = 1.0f / sRow[row0];
    const float inv1 = 1.0f / sRow[row0 + 8];
    float* op = to_h1 ? g_h1 : outp;
    const int coln = head * Dd + wn * 32 + (lane & 3) * 2;
    float* out0 = op + (size_t)(i0 + row0) * HD + coln;
    float* out1 = op + (size_t)(i0 + row0 + 8) * HD + coln;
#pragma unroll
    for (int nt = 0; nt < 4; nt++) {
        float v0 = acc[nt][0] * inv0, v1 = acc[nt][1] * inv0;
        float v2 = acc[nt][2] * inv1, v3 = acc[nt][3] * inv1;
        float2 o0, o1;
        o0.x = (v0 > 0.f) ? v0 : expm1f(v0);
        o0.y = (v1 > 0.f) ? v1 : expm1f(v1);
        o1.x = (v2 > 0.f) ? v2 : expm1f(v2);
        o1.y = (v3 > 0.f) ? v3 : expm1f(v3);
        *reinterpret_cast<float2*>(out0 + nt * 8) = o0;
        *reinterpret_cast<float2*>(out1 + nt * 8) = o1;
    }
}

// =====================================================================
// launch
// =====================================================================
extern "C" void kernel_launch(void* const* d_in, const int* in_sizes, int n_in,
                              void* d_out, int out_size)
{
    (void)in_sizes; (void)n_in; (void)out_size;
    const float* x   = (const float*)d_in[1];
    const int*   adj = (const int*)d_in[2];
    const float* W1  = (const float*)d_in[3];
    const float* a1  = (const float*)d_in[4];
    const float* W2  = (const float*)d_in[5];
    const float* a2  = (const float*)d_in[6];
    float* out = (float*)d_out;

    dim3 gGemm(Nn / 64, Hh);
    dim3 gAttn(Nn / 64, Hh);
    int f12Blocks = (Hh * Nn) / 4;

    pack_adj_kernel<<<(Nn * NW) / 8, 256>>>(adj);

    // ---- layer 1 ----
    feat_gemm_kernel<<<gGemm, 256>>>(x, W1, 0);
    f12_kernel<<<f12Blocks, 128>>>(a1);
    f2max_kernel<<<Hh, 256>>>();
    wprep_kernel<<<(Hh * Nn) / 256, 256>>>();
    attn_mma_kernel<<<gAttn, 256>>>(nullptr, 1);   // -> g_h1

    // ---- layer 2 ----
    feat_gemm_kernel<<<gGemm, 256>>>(nullptr, W2, 1);
    f12_kernel<<<f12Blocks, 128>>>(a2);
    f2max_kernel<<<Hh, 256>>>();
    wprep_kernel<<<(Hh * Nn) / 256, 256>>>();
    attn_mma_kernel<<<gAttn, 256>>>(out, 0);       // -> d_out
}

// round 7
// speedup vs baseline: 1.7788x; 1.0816x over previous
#include <cuda_runtime.h>
#include <cuda_fp16.h>
#include <cstdint>
#include <math.h>

#define Nn 4096
#define Ff 256
#define Dd 64
#define Hh 4
#define HD 256
#define NW 128            // adj bitmask words per row (4096/32)
#define LALPHA 0.2f

// ---------------- scratch (device globals; no allocation) ----------------
__device__ __align__(16) float g_h1[Nn * HD];         // layer-1 output [N][H*D]
__device__ __align__(16) __half g_hTh[Hh * Dd * Nn];  // fp16 hi of h, transposed [H][D][N]
__device__ __align__(16) __half g_hTl[Hh * Dd * Nn];  // fp16 residual lo [H][D][N]
__device__ __align__(16) float g_f1[Hh * Nn];
__device__ __align__(16) float g_f2[Hh * Nn];
__device__ __align__(16) float g_G1[Hh * Nn];
__device__ __align__(16) float g_G1p[Hh * Nn];
__device__ __align__(16) float g_E2[Hh * Nn];
__device__ __align__(16) float g_E2p[Hh * Nn];
__device__ unsigned g_f2maxbits[2 * Hh];
__device__ unsigned g_adjp[Nn * NW];                  // packed adjacency bits

// ---------------- helpers ----------------
static __device__ __forceinline__ uint32_t smem_u32(const void* p) {
    uint32_t a;
    asm("{ .reg .u64 t; cvta.to.shared.u64 t, %1; cvt.u32.u64 %0, t; }" : "=r"(a) : "l"(p));
    return a;
}

static __device__ __forceinline__ uint32_t fkey(float x) {
    unsigned b = __float_as_uint(x);
    return (b & 0x80000000u) ? ~b : (b | 0x80000000u);
}
static __device__ __forceinline__ float fdec(unsigned k) {
    unsigned b = (k & 0x80000000u) ? (k & 0x7FFFFFFFu) : ~k;
    return __uint_as_float(b);
}

static __device__ __forceinline__ uint32_t h2u(__half a, __half b) {
    __half2 p = __halves2half2(a, b);
    return *reinterpret_cast<uint32_t*>(&p);
}

#define LDSM4(R, addr) \
    asm volatile("ldmatrix.sync.aligned.m8n8.x4.shared.b16 {%0,%1,%2,%3}, [%4];" \
                 : "=r"((R)[0]), "=r"((R)[1]), "=r"((R)[2]), "=r"((R)[3]) : "r"(addr))

#define MMA16816(C, A, B0, B1) \
    asm volatile("mma.sync.aligned.m16n8k16.row.col.f32.f16.f16.f32 " \
                 "{%0,%1,%2,%3}, {%4,%5,%6,%7}, {%8,%9}, {%0,%1,%2,%3};" \
                 : "+f"((C)[0]), "+f"((C)[1]), "+f"((C)[2]), "+f"((C)[3]) \
                 : "r"((A)[0]), "r"((A)[1]), "r"((A)[2]), "r"((A)[3]), "r"(B0), "r"(B1))

#define CP16(dst, src) \
    asm volatile("cp.async.ca.shared.global [%0], [%1], 16;" :: "r"(dst), "l"(src))
#define CP_COMMIT() asm volatile("cp.async.commit_group;")
#define CP_WAIT0()  asm volatile("cp.async.wait_group 0;")

#define STS128U(addr, u0, u1, u2, u3) \
    asm volatile("st.shared.v4.b32 [%0], {%1,%2,%3,%4};" \
                 :: "r"(addr), "r"(u0), "r"(u1), "r"(u2), "r"(u3))

// =====================================================================
// K0: pack adjacency into bitmask (+ reset f2max atomics)
// =====================================================================
__global__ void pack_adj_kernel(const int* __restrict__ adj)
{
    if (blockIdx.x == 0 && threadIdx.x < 2 * Hh) g_f2maxbits[threadIdx.x] = 0u;
    int w = blockIdx.x * 8 + (threadIdx.x >> 5);
    int lane = threadIdx.x & 31;
    int v = adj[(size_t)w * 32 + lane];
    unsigned m = __ballot_sync(0xffffffffu, v != 0);
    if (lane == 0) g_adjp[w] = m;
}

// =====================================================================
// K1: feature GEMM  h[h][n][d] = sum_f X[n][f] W[h][f][d]
//   Emits fp16 hi/lo transposed copies, f1/f2 dots, f2 max atomics.
// =====================================================================
__global__ __launch_bounds__(256) void feat_gemm_kernel(
    const float* __restrict__ X, const float* __restrict__ W,
    const float* __restrict__ av, int lay, int use_h1)
{
    const float* Xp = use_h1 ? g_h1 : X;
    const int head = blockIdx.y;
    const int i0 = blockIdx.x * 64;

    __shared__ __align__(16) float sXT[32][68];
    __shared__ __align__(16) float sWs[32][64];
    __shared__ float sa[128];

    const int t = threadIdx.x;
    const int tx = t & 15, ty = t >> 4;
    const int c0 = tx * 4, r0 = ty * 4;

    if (t < 128) sa[t] = av[head * 128 + t];

    float acc[4][4] = {};

    for (int kt = 0; kt < Ff; kt += 32) {
#pragma unroll
        for (int q = 0; q < 2; q++) {
            int idx = t + 256 * q;
            int row = idx >> 3;
            int k0 = (idx & 7) * 4;
            float4 v = *reinterpret_cast<const float4*>(Xp + (size_t)(i0 + row) * Ff + kt + k0);
            sXT[k0 + 0][row] = v.x;
            sXT[k0 + 1][row] = v.y;
            sXT[k0 + 2][row] = v.z;
            sXT[k0 + 3][row] = v.w;
        }
#pragma unroll
        for (int q = 0; q < 2; q++) {
            int idx = t + 256 * q;
            int kk = idx >> 4;
            int cc = (idx & 15) * 4;
            *reinterpret_cast<float4*>(&sWs[kk][cc]) =
                *reinterpret_cast<const float4*>(W + (size_t)(head * Ff + kt + kk) * Dd + cc);
        }
        __syncthreads();
#pragma unroll
        for (int k = 0; k < 32; k++) {
            float4 xv = *reinterpret_cast<const float4*>(&sXT[k][r0]);
            float4 wv = *reinterpret_cast<const float4*>(&sWs[k][c0]);
            acc[0][0] += xv.x * wv.x; acc[0][1] += xv.x * wv.y; acc[0][2] += xv.x * wv.z; acc[0][3] += xv.x * wv.w;
            acc[1][0] += xv.y * wv.x; acc[1][1] += xv.y * wv.y; acc[1][2] += xv.y * wv.z; acc[1][3] += xv.y * wv.w;
            acc[2][0] += xv.z * wv.x; acc[2][1] += xv.z * wv.y; acc[2][2] += xv.z * wv.z; acc[2][3] += xv.z * wv.w;
            acc[3][0] += xv.w * wv.x; acc[3][1] += xv.w * wv.y; acc[3][2] += xv.w * wv.z; acc[3][3] += xv.w * wv.w;
        }
        __syncthreads();
    }

    // ---- fp16 hi/lo transposed copies for MMA B operand ----
#pragma unroll
    for (int r = 0; r < 4; r++) {
#pragma unroll
        for (int c = 0; c < 4; c++) {
            float v = acc[r][c];
            __half hhi = __float2half_rn(v);
            size_t tix = (size_t)(head * Dd + c0 + c) * Nn + i0 + r0 + r;
            g_hTh[tix] = hhi;
            g_hTl[tix] = __float2half_rn(v - __half2float(hhi));
        }
    }

    // ---- fused f1/f2 dots + f2 max ----
    float p1[4], p2[4];
#pragma unroll
    for (int r = 0; r < 4; r++) {
        p1[r] = acc[r][0] * sa[c0] + acc[r][1] * sa[c0 + 1] + acc[r][2] * sa[c0 + 2] + acc[r][3] * sa[c0 + 3];
        p2[r] = acc[r][0] * sa[64 + c0] + acc[r][1] * sa[64 + c0 + 1] + acc[r][2] * sa[64 + c0 + 2] + acc[r][3] * sa[64 + c0 + 3];
#pragma unroll
        for (int o = 1; o < 16; o <<= 1) {
            p1[r] += __shfl_xor_sync(0xffffffffu, p1[r], o);
            p2[r] += __shfl_xor_sync(0xffffffffu, p2[r], o);
        }
    }
    if (tx == 0) {
#pragma unroll
        for (int r = 0; r < 4; r++) {
            g_f1[head * Nn + i0 + r0 + r] = p1[r];
            g_f2[head * Nn + i0 + r0 + r] = p2[r];
        }
    }
    float m = fmaxf(fmaxf(p2[0], p2[1]), fmaxf(p2[2], p2[3]));
#pragma unroll
    for (int o = 16; o; o >>= 1) m = fmaxf(m, __shfl_xor_sync(0xffffffffu, m, o));
    if ((t & 31) == 0) atomicMax(&g_f2maxbits[lay * Hh + head], fkey(m));
}

// =====================================================================
// K4: per-node separable softmax factors
// =====================================================================
__global__ void wprep_kernel(int lay)
{
    int idx = blockIdx.x * 256 + threadIdx.x;
    int head = idx >> 12;
    float f1 = g_f1[idx], f2 = g_f2[idx];
    float m = f1 + fdec(g_f2maxbits[lay * Hh + head]);
    m = (m >= 0.f) ? m : LALPHA * m;
    g_G1[idx]  = expf(f1 - m);
    g_G1p[idx] = expf(LALPHA * f1 - m);
    g_E2[idx]  = expf(f2);
    g_E2p[idx] = expf(LALPHA * f2);
}

// =====================================================================
// K5: attention aggregation, software-pipelined mma.sync (fp16 split, 3 products)
//   M=64 x N=64 per block, K tiles of 32, 2 SMEM stages.
//   grid (Nn/64, Hh), 256 threads, 2 CTAs/SM.
// =====================================================================
__global__ __launch_bounds__(256, 2) void attn_mma_kernel(float* __restrict__ outp, int to_h1)
{
    // [stage][hi/lo][64 rows * 40 halfs]
    __shared__ __align__(16) __half sA[2][2][64 * 40];
    __shared__ __align__(16) __half sB[2][2][64 * 40];
    __shared__ float sRow[64], sF1[64], sG1[64], sG1p[64];

    const int head = blockIdx.y;
    const int i0 = blockIdx.x * 64;
    const int t = threadIdx.x;
    const int lane = t & 31;
    const int wid = t >> 5;

    if (t < 64) {
        int gi = head * Nn + i0 + t;
        sF1[t] = g_f1[gi];
        sG1[t] = g_G1[gi];
        sG1p[t] = g_G1p[gi];
    }

    // ---- generation mapping: r = row (0..63), q = k-octet (8 k each) ----
    const int r = t >> 2, q = t & 3;
    const float* f2b  = g_f2  + head * Nn;
    const float* e2b  = g_E2  + head * Nn;
    const float* e2pb = g_E2p + head * Nn;
    const unsigned* adjrow = g_adjp + (size_t)(i0 + r) * NW;
    const uint32_t gHi = smem_u32(&sA[0][0][r * 40 + q * 8]);   // 16B per tile (8 halfs)
    const uint32_t gLo = gHi + 5120;
    float rsum = 0.f;

    __syncthreads();   // sF1/sG1 visible
    const float f1r = sF1[r], g1 = sG1[r], g1p = sG1p[r];

    // ---- B cp.async mapping: 16 halfs of one (arr, d, k-half) per thread ----
    const int barr = t >> 7;
    const int bs2 = t & 127;
    const int bd = bs2 >> 1;
    const int bkh = (bs2 & 1) * 16;
    const __half* bsrc = (barr ? g_hTl : g_hTh) + (size_t)(head * Dd + bd) * Nn + bkh;
    const uint32_t cB = smem_u32(&sB[0][barr][bd * 40 + bkh]);

    // ---- mma mapping ----
    const int wm = wid & 3, wn = wid >> 2;
    const uint32_t aA  = smem_u32(&sA[0][0][(wm * 16 + (lane & 15)) * 40 + (lane >> 4) * 8]);
    const uint32_t aAl = aA + 5120;
    const uint32_t aB0 = smem_u32(&sB[0][0][(wn * 32 + (lane & 15)) * 40 + (lane >> 4) * 8]);
    const uint32_t aB1 = aB0 + 16 * 40 * 2;
    const uint32_t aB0l = aB0 + 5120;
    const uint32_t aB1l = aB1 + 5120;

    float acc[4][4] = {};

#define GEN_TILE(KT, SOFF) do {                                                     \
        const int kb_ = (KT) * 32;                                                  \
        const unsigned aw_ = adjrow[KT];                                            \
        const int gk_ = kb_ + q * 8;                                                \
        float4 fA = *reinterpret_cast<const float4*>(f2b + gk_);                    \
        float4 fB = *reinterpret_cast<const float4*>(f2b + gk_ + 4);                \
        float4 eA = *reinterpret_cast<const float4*>(e2b + gk_);                    \
        float4 eB = *reinterpret_cast<const float4*>(e2b + gk_ + 4);                \
        float4 pA = *reinterpret_cast<const float4*>(e2pb + gk_);                   \
        float4 pB = *reinterpret_cast<const float4*>(e2pb + gk_ + 4);               \
        const int kq_ = q * 8;                                                      \
        float w0 = ((aw_ >> (kq_ + 0)) & 1) ? ((f1r + fA.x >= 0.f) ? g1 * eA.x : g1p * pA.x) : 0.f; \
        float w1 = ((aw_ >> (kq_ + 1)) & 1) ? ((f1r + fA.y >= 0.f) ? g1 * eA.y : g1p * pA.y) : 0.f; \
        float w2 = ((aw_ >> (kq_ + 2)) & 1) ? ((f1r + fA.z >= 0.f) ? g1 * eA.z : g1p * pA.z) : 0.f; \
        float w3 = ((aw_ >> (kq_ + 3)) & 1) ? ((f1r + fA.w >= 0.f) ? g1 * eA.w : g1p * pA.w) : 0.f; \
        float w4 = ((aw_ >> (kq_ + 4)) & 1) ? ((f1r + fB.x >= 0.f) ? g1 * eB.x : g1p * pB.x) : 0.f; \
        float w5 = ((aw_ >> (kq_ + 5)) & 1) ? ((f1r + fB.y >= 0.f) ? g1 * eB.y : g1p * pB.y) : 0.f; \
        float w6 = ((aw_ >> (kq_ + 6)) & 1) ? ((f1r + fB.z >= 0.f) ? g1 * eB.z : g1p * pB.z) : 0.f; \
        float w7 = ((aw_ >> (kq_ + 7)) & 1) ? ((f1r + fB.w >= 0.f) ? g1 * eB.w : g1p * pB.w) : 0.f; \
        rsum += ((w0 + w1) + (w2 + w3)) + ((w4 + w5) + (w6 + w7));                  \
        __half h0 = __float2half_rn(w0), h1 = __float2half_rn(w1);                  \
        __half h2 = __float2half_rn(w2), h3 = __float2half_rn(w3);                  \
        __half h4 = __float2half_rn(w4), h5 = __float2half_rn(w5);                  \
        __half h6 = __float2half_rn(w6), h7 = __float2half_rn(w7);                  \
        STS128U(gHi + (SOFF), h2u(h0, h1), h2u(h2, h3), h2u(h4, h5), h2u(h6, h7));  \
        __half l0 = __float2half_rn(w0 - __half2float(h0));                         \
        __half l1 = __float2half_rn(w1 - __half2float(h1));                         \
        __half l2 = __float2half_rn(w2 - __half2float(h2));                         \
        __half l3 = __float2half_rn(w3 - __half2float(h3));                         \
        __half l4 = __float2half_rn(w4 - __half2float(h4));                         \
        __half l5 = __float2half_rn(w5 - __half2float(h5));                         \
        __half l6 = __float2half_rn(w6 - __half2float(h6));                         \
        __half l7 = __float2half_rn(w7 - __half2float(h7));                         \
        STS128U(gLo + (SOFF), h2u(l0, l1), h2u(l2, l3), h2u(l4, l5), h2u(l6, l7));  \
    } while (0)

    // ---- prologue: fill stage 0 ----
    CP16(cB, bsrc);
    CP16(cB + 16, bsrc + 8);
    CP_COMMIT();
    GEN_TILE(0, 0);
    CP_WAIT0();
    __syncthreads();

    for (int kt = 0; kt < NW; kt++) {
        const int s = kt & 1;
        const uint32_t so = (uint32_t)s * 10240u;
        const uint32_t nso = so ^ 10240u;

        if (kt + 1 < NW) {
            const __half* src = bsrc + (kt + 1) * 32;
            CP16(cB + nso, src);
            CP16(cB + nso + 16, src + 8);
            CP_COMMIT();
            GEN_TILE(kt + 1, nso);
        }

        // ---- mma on stage s ----
        uint32_t ah[4], al[4], bh[4], bl[4];
#pragma unroll
        for (int kk = 0; kk < 2; kk++) {
            const uint32_t ko = so + kk * 32;
            LDSM4(ah, aA + ko);
            LDSM4(al, aAl + ko);
            LDSM4(bh, aB0 + ko);
            LDSM4(bl, aB0l + ko);
            MMA16816(acc[0], ah, bh[0], bh[2]);
            MMA16816(acc[1], ah, bh[1], bh[3]);
            MMA16816(acc[0], al, bh[0], bh[2]);
            MMA16816(acc[1], al, bh[1], bh[3]);
            MMA16816(acc[0], ah, bl[0], bl[2]);
            MMA16816(acc[1], ah, bl[1], bl[3]);
            LDSM4(bh, aB1 + ko);
            LDSM4(bl, aB1l + ko);
            MMA16816(acc[2], ah, bh[0], bh[2]);
            MMA16816(acc[3], ah, bh[1], bh[3]);
            MMA16816(acc[2], al, bh[0], bh[2]);
            MMA16816(acc[3], al, bh[1], bh[3]);
            MMA16816(acc[2], ah, bl[0], bl[2]);
            MMA16816(acc[3], ah, bl[1], bl[3]);
        }

        if (kt + 1 < NW) CP_WAIT0();
        __syncthreads();
    }

    // ---- rowsum finalize (exact fp32) ----
    rsum += __shfl_xor_sync(0xffffffffu, rsum, 1);
    rsum += __shfl_xor_sync(0xffffffffu, rsum, 2);
    if (q == 0) sRow[r] = rsum;
    __syncthreads();

    // ---- epilogue: normalize + ELU + store ----
    const int g = lane >> 2;
    const int row0 = wm * 16 + g;
    const float inv0 = 1.0f / sRow[row0];
    const float inv1 = 1.0f / sRow[row0 + 8];
    float* op = to_h1 ? g_h1 : outp;
    const int coln = head * Dd + wn * 32 + (lane & 3) * 2;
    float* out0 = op + (size_t)(i0 + row0) * HD + coln;
    float* out1 = op + (size_t)(i0 + row0 + 8) * HD + coln;
#pragma unroll
    for (int nt = 0; nt < 4; nt++) {
        float v0 = acc[nt][0] * inv0, v1 = acc[nt][1] * inv0;
        float v2 = acc[nt][2] * inv1, v3 = acc[nt][3] * inv1;
        float2 o0, o1;
        o0.x = (v0 > 0.f) ? v0 : expm1f(v0);
        o0.y = (v1 > 0.f) ? v1 : expm1f(v1);
        o1.x = (v2 > 0.f) ? v2 : expm1f(v2);
        o1.y = (v3 > 0.f) ? v3 : expm1f(v3);
        *reinterpret_cast<float2*>(out0 + nt * 8) = o0;
        *reinterpret_cast<float2*>(out1 + nt * 8) = o1;
    }
}

// =====================================================================
// launch
// =====================================================================
extern "C" void kernel_launch(void* const* d_in, const int* in_sizes, int n_in,
                              void* d_out, int out_size)
{
    (void)in_sizes; (void)n_in; (void)out_size;
    const float* x   = (const float*)d_in[1];
    const int*   adj = (const int*)d_in[2];
    const float* W1  = (const float*)d_in[3];
    const float* a1  = (const float*)d_in[4];
    const float* W2  = (const float*)d_in[5];
    const float* a2  = (const float*)d_in[6];
    float* out = (float*)d_out;

    dim3 gGemm(Nn / 64, Hh);
    dim3 gAttn(Nn / 64, Hh);

    pack_adj_kernel<<<(Nn * NW) / 8, 256>>>(adj);

    // ---- layer 1 ----
    feat_gemm_kernel<<<gGemm, 256>>>(x, W1, a1, 0, 0);
    wprep_kernel<<<(Hh * Nn) / 256, 256>>>(0);
    attn_mma_kernel<<<gAttn, 256>>>(nullptr, 1);   // -> g_h1

    // ---- layer 2 ----
    feat_gemm_kernel<<<gGemm, 256>>>(nullptr, W2, a2, 1, 1);
    wprep_kernel<<<(Hh * Nn) / 256, 256>>>(1);
    attn_mma_kernel<<<gAttn, 256>>>(out, 0);       // -> d_out
}

// round 9
// speedup vs baseline: 1.8148x; 1.0202x over previous
#include <cuda_runtime.h>
#include <cuda_fp16.h>
#include <cstdint>
#include <math.h>

#define Nn 4096
#define Ff 256
#define Dd 64
#define Hh 4
#define HD 256
#define NW 128            // adj bitmask words per row (4096/32)
#define LALPHA 0.2f

// ---------------- scratch (device globals; no allocation) ----------------
__device__ __align__(16) float g_h1[Nn * HD];         // layer-1 output [N][H*D]
__device__ __align__(16) __half g_hTh[Hh * Dd * Nn];  // fp16 hi of h, transposed [H][D][N]
__device__ __align__(16) __half g_hTl[Hh * Dd * Nn];  // fp16 residual lo [H][D][N]
__device__ __align__(16) float g_f1[Hh * Nn];
__device__ __align__(16) float g_f2[Hh * Nn];
__device__ __align__(16) float g_G1[Hh * Nn];
__device__ __align__(16) float g_G1p[Hh * Nn];
__device__ __align__(16) float g_E2[Hh * Nn];
__device__ __align__(16) float g_E2p[Hh * Nn];
__device__ unsigned g_f2maxbits[2 * Hh];
__device__ unsigned g_adjp[Nn * NW];                  // packed adjacency bits

// ---------------- helpers ----------------
static __device__ __forceinline__ uint32_t smem_u32(const void* p) {
    uint32_t a;
    asm("{ .reg .u64 t; cvta.to.shared.u64 t, %1; cvt.u32.u64 %0, t; }" : "=r"(a) : "l"(p));
    return a;
}

static __device__ __forceinline__ uint32_t fkey(float x) {
    unsigned b = __float_as_uint(x);
    return (b & 0x80000000u) ? ~b : (b | 0x80000000u);
}
static __device__ __forceinline__ float fdec(unsigned k) {
    unsigned b = (k & 0x80000000u) ? (k & 0x7FFFFFFFu) : ~k;
    return __uint_as_float(b);
}

static __device__ __forceinline__ uint32_t u32h2(__half2 p) {
    return *reinterpret_cast<uint32_t*>(&p);
}

#define LDSM4(R, addr) \
    asm volatile("ldmatrix.sync.aligned.m8n8.x4.shared.b16 {%0,%1,%2,%3}, [%4];" \
                 : "=r"((R)[0]), "=r"((R)[1]), "=r"((R)[2]), "=r"((R)[3]) : "r"(addr))

#define MMA16816(C, A, B0, B1) \
    asm volatile("mma.sync.aligned.m16n8k16.row.col.f32.f16.f16.f32 " \
                 "{%0,%1,%2,%3}, {%4,%5,%6,%7}, {%8,%9}, {%0,%1,%2,%3};" \
                 : "+f"((C)[0]), "+f"((C)[1]), "+f"((C)[2]), "+f"((C)[3]) \
                 : "r"((A)[0]), "r"((A)[1]), "r"((A)[2]), "r"((A)[3]), "r"(B0), "r"(B1))

#define CP16(dst, src) \
    asm volatile("cp.async.ca.shared.global [%0], [%1], 16;" :: "r"(dst), "l"(src))
#define CP_COMMIT() asm volatile("cp.async.commit_group;")
#define CP_WAIT0()  asm volatile("cp.async.wait_group 0;")

// =====================================================================
// K0: pack adjacency into bitmask (+ reset f2max atomics)
// =====================================================================
__global__ void pack_adj_kernel(const int* __restrict__ adj)
{
    if (blockIdx.x == 0 && threadIdx.x < 2 * Hh) g_f2maxbits[threadIdx.x] = 0u;
    int w = blockIdx.x * 8 + (threadIdx.x >> 5);
    int lane = threadIdx.x & 31;
    int v = adj[(size_t)w * 32 + lane];
    unsigned m = __ballot_sync(0xffffffffu, v != 0);
    if (lane == 0) g_adjp[w] = m;
}

// =====================================================================
// K1: feature GEMM  h[h][n][d] = sum_f X[n][f] W[h][f][d]
//   Emits fp16 hi/lo transposed copies, f1/f2 dots, f2 max atomics.
// =====================================================================
__global__ __launch_bounds__(256) void feat_gemm_kernel(
    const float* __restrict__ X, const float* __restrict__ W,
    const float* __restrict__ av, int lay, int use_h1)
{
    const float* Xp = use_h1 ? g_h1 : X;
    const int head = blockIdx.y;
    const int i0 = blockIdx.x * 64;

    __shared__ __align__(16) float sXT[32][68];
    __shared__ __align__(16) float sWs[32][64];
    __shared__ float sa[128];

    const int t = threadIdx.x;
    const int tx = t & 15, ty = t >> 4;
    const int c0 = tx * 4, r0 = ty * 4;

    if (t < 128) sa[t] = av[head * 128 + t];

    float acc[4][4] = {};

    for (int kt = 0; kt < Ff; kt += 32) {
#pragma unroll
        for (int q = 0; q < 2; q++) {
            int idx = t + 256 * q;
            int row = idx >> 3;
            int k0 = (idx & 7) * 4;
            float4 v = *reinterpret_cast<const float4*>(Xp + (size_t)(i0 + row) * Ff + kt + k0);
            sXT[k0 + 0][row] = v.x;
            sXT[k0 + 1][row] = v.y;
            sXT[k0 + 2][row] = v.z;
            sXT[k0 + 3][row] = v.w;
        }
#pragma unroll
        for (int q = 0; q < 2; q++) {
            int idx = t + 256 * q;
            int kk = idx >> 4;
            int cc = (idx & 15) * 4;
            *reinterpret_cast<float4*>(&sWs[kk][cc]) =
                *reinterpret_cast<const float4*>(W + (size_t)(head * Ff + kt + kk) * Dd + cc);
        }
        __syncthreads();
#pragma unroll
        for (int k = 0; k < 32; k++) {
            float4 xv = *reinterpret_cast<const float4*>(&sXT[k][r0]);
            float4 wv = *reinterpret_cast<const float4*>(&sWs[k][c0]);
            acc[0][0] += xv.x * wv.x; acc[0][1] += xv.x * wv.y; acc[0][2] += xv.x * wv.z; acc[0][3] += xv.x * wv.w;
            acc[1][0] += xv.y * wv.x; acc[1][1] += xv.y * wv.y; acc[1][2] += xv.y * wv.z; acc[1][3] += xv.y * wv.w;
            acc[2][0] += xv.z * wv.x; acc[2][1] += xv.z * wv.y; acc[2][2] += xv.z * wv.z; acc[2][3] += xv.z * wv.w;
            acc[3][0] += xv.w * wv.x; acc[3][1] += xv.w * wv.y; acc[3][2] += xv.w * wv.z; acc[3][3] += xv.w * wv.w;
        }
        __syncthreads();
    }

    // ---- fp16 hi/lo transposed copies for MMA B operand ----
#pragma unroll
    for (int r = 0; r < 4; r++) {
#pragma unroll
        for (int c = 0; c < 4; c++) {
            float v = acc[r][c];
            __half hhi = __float2half_rn(v);
            size_t tix = (size_t)(head * Dd + c0 + c) * Nn + i0 + r0 + r;
            g_hTh[tix] = hhi;
            g_hTl[tix] = __float2half_rn(v - __half2float(hhi));
        }
    }

    // ---- fused f1/f2 dots + f2 max ----
    float p1[4], p2[4];
#pragma unroll
    for (int r = 0; r < 4; r++) {
        p1[r] = acc[r][0] * sa[c0] + acc[r][1] * sa[c0 + 1] + acc[r][2] * sa[c0 + 2] + acc[r][3] * sa[c0 + 3];
        p2[r] = acc[r][0] * sa[64 + c0] + acc[r][1] * sa[64 + c0 + 1] + acc[r][2] * sa[64 + c0 + 2] + acc[r][3] * sa[64 + c0 + 3];
#pragma unroll
        for (int o = 1; o < 16; o <<= 1) {
            p1[r] += __shfl_xor_sync(0xffffffffu, p1[r], o);
            p2[r] += __shfl_xor_sync(0xffffffffu, p2[r], o);
        }
    }
    if (tx == 0) {
#pragma unroll
        for (int r = 0; r < 4; r++) {
            g_f1[head * Nn + i0 + r0 + r] = p1[r];
            g_f2[head * Nn + i0 + r0 + r] = p2[r];
        }
    }
    float m = fmaxf(fmaxf(p2[0], p2[1]), fmaxf(p2[2], p2[3]));
#pragma unroll
    for (int o = 16; o; o >>= 1) m = fmaxf(m, __shfl_xor_sync(0xffffffffu, m, o));
    if ((t & 31) == 0) atomicMax(&g_f2maxbits[lay * Hh + head], fkey(m));
}

// =====================================================================
// K4: per-node separable softmax factors
// =====================================================================
__global__ void wprep_kernel(int lay)
{
    int idx = blockIdx.x * 256 + threadIdx.x;
    int head = idx >> 12;
    float f1 = g_f1[idx], f2 = g_f2[idx];
    float m = f1 + fdec(g_f2maxbits[lay * Hh + head]);
    m = (m >= 0.f) ? m : LALPHA * m;
    g_G1[idx]  = expf(f1 - m);
    g_G1p[idx] = expf(LALPHA * f1 - m);
    g_E2[idx]  = expf(f2);
    g_E2p[idx] = expf(LALPHA * f2);
}

// =====================================================================
// K5: attention aggregation, register-direct A fragments (fp16 split, 3 products)
//   CTA: 128 threads, 4 warps. M=64 (16 rows/warp), N=64, K tiles of 32.
//   A fragments generated straight into registers (no A SMEM at all).
//   B double-buffered in SMEM via cp.async.
// =====================================================================
__global__ __launch_bounds__(128, 3) void attn_mma_kernel(float* __restrict__ outp, int to_h1)
{
    // B tiles: [stage][hi/lo][64 n * 40 halfs]
    __shared__ __align__(16) __half sB[2][2][64 * 40];

    const int head = blockIdx.y;
    const int i0 = blockIdx.x * 64;
    const int t = threadIdx.x;
    const int lane = t & 31;
    const int wid = t >> 5;

    const int g = lane >> 2;
    const int c2 = (lane & 3) * 2;
    const int r0 = wid * 16 + g;
    const int r1 = r0 + 8;

    // per-row softmax factors (registers, straight from global)
    const int gi0 = head * Nn + i0 + r0;
    const int gi1 = head * Nn + i0 + r1;
    const float f1a = g_f1[gi0], g1a = g_G1[gi0], g1pa = g_G1p[gi0];
    const float f1b = g_f1[gi1], g1b = g_G1[gi1], g1pb = g_G1p[gi1];

    const unsigned* adj0 = g_adjp + (size_t)(i0 + r0) * NW;
    const unsigned* adj1 = g_adjp + (size_t)(i0 + r1) * NW;

    const float* f2b  = g_f2  + head * Nn;
    const float* e2b  = g_E2  + head * Nn;
    const float* e2pb = g_E2p + head * Nn;

    // ---- B cp.async mapping: thread t copies one (hilo, n-row): 64B = 4x16B ----
    const int barr = t >> 6;
    const int bd = t & 63;
    const __half* bsrc = (barr ? g_hTl : g_hTh) + (size_t)(head * Dd + bd) * Nn;
    const uint32_t cB = smem_u32(&sB[0][barr][bd * 40]);

    // ---- LDSM base for B: row (lane&15), col (lane>>4)*8 halfs ----
    const uint32_t aB = smem_u32(&sB[0][0][(lane & 15) * 40 + (lane >> 4) * 8]);
    // offsets: stage +10240B, hilo +5120B, 16-row group +1280B, k-step +32B

    float acc[8][4] = {};
    float rs0 = 0.f, rs1 = 0.f;
    uint32_t aH0[2][4], aL0[2][4], aH1[2][4], aL1[2][4];

#define COPYB(KT, ST) do {                                                    \
        const __half* s_ = bsrc + (KT) * 32;                                  \
        uint32_t d_ = cB + (ST) * 10240u;                                     \
        CP16(d_, s_); CP16(d_ + 16, s_ + 8);                                  \
        CP16(d_ + 32, s_ + 16); CP16(d_ + 48, s_ + 24);                       \
    } while (0)

#define GENK(AW0, AW1, KB, SH, AHK, ALK) do {                                 \
        float2 fA = *reinterpret_cast<const float2*>(f2b + (KB) + c2);        \
        float2 fC = *reinterpret_cast<const float2*>(f2b + (KB) + 8 + c2);    \
        float2 eA = *reinterpret_cast<const float2*>(e2b + (KB) + c2);        \
        float2 eC = *reinterpret_cast<const float2*>(e2b + (KB) + 8 + c2);    \
        float2 pA = *reinterpret_cast<const float2*>(e2pb + (KB) + c2);       \
        float2 pC = *reinterpret_cast<const float2*>(e2pb + (KB) + 8 + c2);   \
        float w00 = (((AW0) >> (SH)) & 1u)       ? ((f1a + fA.x >= 0.f) ? g1a * eA.x : g1pa * pA.x) : 0.f; \
        float w01 = (((AW0) >> ((SH) + 1)) & 1u) ? ((f1a + fA.y >= 0.f) ? g1a * eA.y : g1pa * pA.y) : 0.f; \
        float w02 = (((AW0) >> ((SH) + 8)) & 1u) ? ((f1a + fC.x >= 0.f) ? g1a * eC.x : g1pa * pC.x) : 0.f; \
        float w03 = (((AW0) >> ((SH) + 9)) & 1u) ? ((f1a + fC.y >= 0.f) ? g1a * eC.y : g1pa * pC.y) : 0.f; \
        float w10 = (((AW1) >> (SH)) & 1u)       ? ((f1b + fA.x >= 0.f) ? g1b * eA.x : g1pb * pA.x) : 0.f; \
        float w11 = (((AW1) >> ((SH) + 1)) & 1u) ? ((f1b + fA.y >= 0.f) ? g1b * eA.y : g1pb * pA.y) : 0.f; \
        float w12 = (((AW1) >> ((SH) + 8)) & 1u) ? ((f1b + fC.x >= 0.f) ? g1b * eC.x : g1pb * pC.x) : 0.f; \
        float w13 = (((AW1) >> ((SH) + 9)) & 1u) ? ((f1b + fC.y >= 0.f) ? g1b * eC.y : g1pb * pC.y) : 0.f; \
        rs0 += (w00 + w01) + (w02 + w03);                                     \
        rs1 += (w10 + w11) + (w12 + w13);                                     \
        __half2 H0 = __float22half2_rn(make_float2(w00, w01));                \
        __half2 H1 = __float22half2_rn(make_float2(w10, w11));                \
        __half2 H2 = __float22half2_rn(make_float2(w02, w03));                \
        __half2 H3 = __float22half2_rn(make_float2(w12, w13));                \
        float2 x0 = __half22float2(H0), x1 = __half22float2(H1);              \
        float2 x2 = __half22float2(H2), x3 = __half22float2(H3);              \
        (AHK)[0] = u32h2(H0); (AHK)[1] = u32h2(H1);                           \
        (AHK)[2] = u32h2(H2); (AHK)[3] = u32h2(H3);                           \
        (ALK)[0] = u32h2(__float22half2_rn(make_float2(w00 - x0.x, w01 - x0.y))); \
        (ALK)[1] = u32h2(__float22half2_rn(make_float2(w10 - x1.x, w11 - x1.y))); \
        (ALK)[2] = u32h2(__float22half2_rn(make_float2(w02 - x2.x, w03 - x2.y))); \
        (ALK)[3] = u32h2(__float22half2_rn(make_float2(w12 - x3.x, w13 - x3.y))); \
    } while (0)

#define GEN_TILE(KT, AH, AL) do {                                             \
        const unsigned awa_ = adj0[KT], awb_ = adj1[KT];                      \
        GENK(awa_, awb_, (KT) * 32,      c2,      (AH)[0], (AL)[0]);          \
        GENK(awa_, awb_, (KT) * 32 + 16, c2 + 16, (AH)[1], (AL)[1]);          \
    } while (0)

#define MMATILE(SO, AH, AL) do {                                              \
        _Pragma("unroll")                                                     \
        for (int kk_ = 0; kk_ < 2; kk_++) {                                   \
            const uint32_t ko_ = (SO) + kk_ * 32;                             \
            _Pragma("unroll")                                                 \
            for (int j_ = 0; j_ < 4; j_++) {                                  \
                uint32_t bh_[4], bl_[4];                                      \
                LDSM4(bh_, aB + ko_ + j_ * 1280);                             \
                LDSM4(bl_, aB + ko_ + j_ * 1280 + 5120);                      \
                MMA16816(acc[2 * j_],     (AH)[kk_], bh_[0], bh_[2]);         \
                MMA16816(acc[2 * j_ + 1], (AH)[kk_], bh_[1], bh_[3]);         \
                MMA16816(acc[2 * j_],     (AL)[kk_], bh_[0], bh_[2]);         \
                MMA16816(acc[2 * j_ + 1], (AL)[kk_], bh_[1], bh_[3]);         \
                MMA16816(acc[2 * j_],     (AH)[kk_], bl_[0], bl_[2]);         \
                MMA16816(acc[2 * j_ + 1], (AH)[kk_], bl_[1], bl_[3]);         \
            }                                                                 \
        }                                                                     \
    } while (0)

    // ---- prologue ----
    COPYB(0, 0);
    CP_COMMIT();
    GEN_TILE(0, aH0, aL0);
    CP_WAIT0();
    __syncthreads();

#pragma unroll 1
    for (int kt = 0; kt < NW; kt += 2) {
        if (kt + 1 < NW) {
            COPYB(kt + 1, 1);
            CP_COMMIT();
            GEN_TILE(kt + 1, aH1, aL1);
        }
        MMATILE(0u, aH0, aL0);
        CP_WAIT0();
        __syncthreads();

        if (kt + 2 < NW) {
            COPYB(kt + 2, 0);
            CP_COMMIT();
            GEN_TILE(kt + 2, aH0, aL0);
        }
        MMATILE(10240u, aH1, aL1);
        CP_WAIT0();
        __syncthreads();
    }

    // ---- rowsum finalize: reduce across the 4 lanes sharing each row ----
    rs0 += __shfl_xor_sync(0xffffffffu, rs0, 1);
    rs0 += __shfl_xor_sync(0xffffffffu, rs0, 2);
    rs1 += __shfl_xor_sync(0xffffffffu, rs1, 1);
    rs1 += __shfl_xor_sync(0xffffffffu, rs1, 2);
    const float inv0 = 1.0f / rs0;
    const float inv1 = 1.0f / rs1;

    // ---- epilogue: normalize + ELU + store ----
    float* op = to_h1 ? g_h1 : outp;
    float* o0 = op + (size_t)(i0 + r0) * HD + head * Dd + c2;
    float* o1 = op + (size_t)(i0 + r1) * HD + head * Dd + c2;
#pragma unroll
    for (int oct = 0; oct < 8; oct++) {
        float v0 = acc[oct][0] * inv0, v1 = acc[oct][1] * inv0;
        float v2 = acc[oct][2] * inv1, v3 = acc[oct][3] * inv1;
        float2 q0, q1;
        q0.x = (v0 > 0.f) ? v0 : expm1f(v0);
        q0.y = (v1 > 0.f) ? v1 : expm1f(v1);
        q1.x = (v2 > 0.f) ? v2 : expm1f(v2);
        q1.y = (v3 > 0.f) ? v3 : expm1f(v3);
        *reinterpret_cast<float2*>(o0 + oct * 8) = q0;
        *reinterpret_cast<float2*>(o1 + oct * 8) = q1;
    }
}

// =====================================================================
// launch
// =====================================================================
extern "C" void kernel_launch(void* const* d_in, const int* in_sizes, int n_in,
                              void* d_out, int out_size)
{
    (void)in_sizes; (void)n_in; (void)out_size;
    const float* x   = (const float*)d_in[1];
    const int*   adj = (const int*)d_in[2];
    const float* W1  = (const float*)d_in[3];
    const float* a1  = (const float*)d_in[4];
    const float* W2  = (const float*)d_in[5];
    const float* a2  = (const float*)d_in[6];
    float* out = (float*)d_out;

    dim3 gGemm(Nn / 64, Hh);
    dim3 gAttn(Nn / 64, Hh);

    pack_adj_kernel<<<(Nn * NW) / 8, 256>>>(adj);

    // ---- layer 1 ----
    feat_gemm_kernel<<<gGemm, 256>>>(x, W1, a1, 0, 0);
    wprep_kernel<<<(Hh * Nn) / 256, 256>>>(0);
    attn_mma_kernel<<<gAttn, 128>>>(nullptr, 1);   // -> g_h1

    // ---- layer 2 ----
    feat_gemm_kernel<<<gGemm, 256>>>(nullptr, W2, a2, 1, 1);
    wprep_kernel<<<(Hh * Nn) / 256, 256>>>(1);
    attn_mma_kernel<<<gAttn, 128>>>(out, 0);       // -> d_out
}